// round 16
// baseline (speedup 1.0000x reference)
#include <cuda_runtime.h>
#include <math.h>

#define LTOT    19530
#define BB      64
#define SS      32
#define NROWS   2048
#define NBISECT 32
#define N4      4882        // full float4-column groups per row (4*4882 = 19528)
#define NTILE_B 39          // 128-wide float4-group tiles per row (39*128=4992 >= 4883)
#define NTILES  (BB * NTILE_B)
#define SCT     128         // k_scale threads per block

// Scratch (__device__ global: allocation-guard compliant)
__device__ float g_pw[NROWS * 8];   // per-row root powers [row][k] = root^k

// ---------------------------------------------------------------------------
// Kernel 1: per-row per-level squared sums + fused bisection (frozen R3 form)
// ---------------------------------------------------------------------------
__device__ __forceinline__ void vec_sq_sum(const float* __restrict__ x,
                                           int lo, int hi, int p,
                                           int tid, float& acc) {
    int a = lo + ((((p - lo) % 4) + 4) % 4);
    if (tid < a - lo) { float v = x[lo + tid]; acc = fmaf(v, v, acc); }
    const int nv = (hi - a) >> 2;
    const float4* __restrict__ xv = (const float4*)(x + a);
    #pragma unroll 4
    for (int i = tid; i < nv; i += 256) {
        float4 v = xv[i];
        acc = fmaf(v.x, v.x, acc);
        acc = fmaf(v.y, v.y, acc);
        acc = fmaf(v.z, v.z, acc);
        acc = fmaf(v.w, v.w, acc);
    }
    const int t0 = a + 4 * nv;
    if (tid < hi - t0) { float v = x[t0 + tid]; acc = fmaf(v, v, acc); }
}

__global__ __launch_bounds__(256) void k_levelsums(const float* __restrict__ sig) {
    const int row = blockIdx.x;
    const int tid = threadIdx.x;
    const float* __restrict__ x = sig + (size_t)row * LTOT;

    float acc[6] = {0.f, 0.f, 0.f, 0.f, 0.f, 0.f};

    const int off[5] = {0, 5, 30, 155, 780};
    #pragma unroll
    for (int k = 0; k < 4; k++)
        for (int i = off[k] + tid; i < off[k + 1]; i += 256) {
            float v = x[i];
            acc[k] = fmaf(v, v, acc[k]);
        }

    const int p = (row & 1) ? 2 : 0;   // row byte base % 16 == 8 for odd rows
    vec_sq_sum(x, 780,  3905, p, tid, acc[4]);
    vec_sq_sum(x, 3905, LTOT, p, tid, acc[5]);

    __shared__ float sm[8][8];
    __shared__ float totals[8];
    const int lane = tid & 31, w = tid >> 5;
    #pragma unroll
    for (int k = 0; k < 6; k++) {
        float v = acc[k];
        #pragma unroll
        for (int o = 16; o > 0; o >>= 1) v += __shfl_down_sync(0xffffffffu, v, o);
        if (lane == 0) sm[w][k] = v;
    }
    __syncthreads();
    if (w == 0) {
        if (lane < 6) {
            float t = 0.f;
            #pragma unroll
            for (int i = 0; i < 8; i++) t += sm[i][lane];
            totals[lane] = t;
        }
        __syncwarp();
        if (lane == 0) {
            float c[7];
            float total = 0.f;
            #pragma unroll
            for (int k = 1; k <= 6; k++) { c[k] = totals[k - 1]; total += c[k]; }
            const float nq  = 1.f + total;
            const float phi = (nq > 4.f) ? (8.f - 16.f / nq) : nq;   // C=4, a=1
            c[0] = 1.f - phi;

            bool fin = true;
            #pragma unroll
            for (int k = 0; k < 7; k++) fin = fin && isfinite(c[k]);

            float lo = 0.f, hi = 2.f;
            #pragma unroll 4
            for (int it = 0; it < NBISECT; it++) {
                const float mid = 0.5f * (lo + hi);
                const float u   = mid * mid;
                float pz = c[6];
                #pragma unroll
                for (int k = 5; k >= 0; k--) pz = fmaf(pz, u, c[k]);
                const bool neg = pz < 0.f;
                lo = neg ? mid : lo;
                hi = neg ? hi  : mid;
            }
            float root = 0.5f * (lo + hi);
            if (!fin) root = 0.f;
            root = fminf(root, 1.f);

            float pw = 1.f;
            g_pw[row * 8 + 0] = 1.f;
            #pragma unroll
            for (int k = 1; k <= 6; k++) { pw *= root; g_pw[row * 8 + k] = pw; }
            g_pw[row * 8 + 7] = 0.f;
        }
    }
}

// ---------------------------------------------------------------------------
// Kernel 2: scale + mean over S. 128-thread blocks, 39 tiles/row (finer wave
// quantization). All-LDG.128 with shifted odd-row loads + smem shift-add.
// Tail thread sums EVEN samples only. Reverse tile order for L2 reuse.
// ---------------------------------------------------------------------------
__device__ __forceinline__ int level_of(int idx) {
    if (idx < 5)    return 1;
    if (idx < 30)   return 2;
    if (idx < 155)  return 3;
    if (idx < 780)  return 4;
    if (idx < 3905) return 5;
    return 6;
}

__global__ __launch_bounds__(SCT, 8) void k_scale(const float* __restrict__ sig,
                                                  float* __restrict__ out) {
    const int rtile = (NTILES - 1) - (int)blockIdx.x;   // high tiles first
    const int b  = rtile / NTILE_B;
    const int tt = rtile - b * NTILE_B;
    const int tid = threadIdx.x;

    __shared__ float spw[SS * 8];
    __shared__ float sh[4 * SCT + 4];   // shifted odd-row sums, by column offset

    #pragma unroll
    for (int i = tid; i < SS * 8; i += SCT)
        spw[i] = g_pw[(size_t)b * SS * 8 + i];
    __syncthreads();

    const int j4 = tt * SCT + tid;
    const int e0 = 4 * j4;
    const bool full = (j4 < N4);
    const bool tail = (j4 == N4);

    const float* __restrict__ base = sig + (size_t)b * SS * LTOT;
    const float inv = 1.f / (float)SS;

    float a0 = 0.f, a1 = 0.f, a2 = 0.f, a3 = 0.f;       // cols e0..e0+3
    float c0 = 0.f, c1 = 0.f, c2 = 0.f, c3 = 0.f;       // odd rows, cols e0+2..e0+5
    float h0 = 0.f, h1 = 0.f;                           // halo: first 2 cols, odd rows

    if (full) {
        const int lv0 = level_of(e0);
        const int lv1 = level_of(e0 + 1);
        const int lv2 = level_of(e0 + 2);
        const int lv3 = level_of(e0 + 3);
        const int lv4 = level_of(e0 + 4);
        const int lv5 = level_of(e0 + 5);

        #pragma unroll
        for (int sb = 0; sb < SS; sb += 8) {
            // 8 x LDG.128, all 16B-aligned, front-batched
            float4 ue[4], uo[4];
            #pragma unroll
            for (int t = 0; t < 4; t++)
                ue[t] = *(const float4*)(base + (size_t)(sb + 2 * t) * LTOT + e0);
            #pragma unroll
            for (int t = 0; t < 4; t++)
                uo[t] = *(const float4*)(base + (size_t)(sb + 2 * t + 1) * LTOT + e0 + 2);
            #pragma unroll
            for (int t = 0; t < 4; t++) {
                const int se = sb + 2 * t, so = se + 1;
                a0 = fmaf(ue[t].x, spw[se * 8 + lv0], a0);
                a1 = fmaf(ue[t].y, spw[se * 8 + lv1], a1);
                a2 = fmaf(ue[t].z, spw[se * 8 + lv2], a2);
                a3 = fmaf(ue[t].w, spw[se * 8 + lv3], a3);
                c0 = fmaf(uo[t].x, spw[so * 8 + lv2], c0);
                c1 = fmaf(uo[t].y, spw[so * 8 + lv3], c1);
                c2 = fmaf(uo[t].z, spw[so * 8 + lv4], c2);
                c3 = fmaf(uo[t].w, spw[so * 8 + lv5], c3);
            }
        }
        if (tid == 0) {
            // halo: odd rows' first two columns of this block's tile
            #pragma unroll
            for (int s = 1; s < SS; s += 2) {
                const float2 v = *(const float2*)(base + (size_t)s * LTOT + e0);
                h0 = fmaf(v.x, spw[s * 8 + lv0], h0);
                h1 = fmaf(v.y, spw[s * 8 + lv1], h1);
            }
        }
    } else if (tail) {
        // cols 19528/19529 (level 6): EVEN rows only — odd rows come from
        // the previous thread's shifted c2/c3 via sh.
        #pragma unroll
        for (int s = 0; s < SS; s += 2) {
            const float2 v = *(const float2*)(base + (size_t)s * LTOT + e0);
            const float  w6 = spw[s * 8 + 6];
            a0 = fmaf(v.x, w6, a0);
            a1 = fmaf(v.y, w6, a1);
        }
    }

    // column-offset shift: thread t's c_i sit at column offset 4t+2+i
    if (tid == 0) { sh[0] = h0; sh[1] = h1; }
    sh[4 * tid + 2] = full ? c0 : 0.f;
    sh[4 * tid + 3] = full ? c1 : 0.f;
    sh[4 * tid + 4] = full ? c2 : 0.f;
    sh[4 * tid + 5] = full ? c3 : 0.f;
    __syncthreads();

    if (full) {
        float* o = out + (size_t)b * LTOT + e0;   // 8B aligned
        *(float2*)o       = make_float2((a0 + sh[4 * tid])     * inv,
                                        (a1 + sh[4 * tid + 1]) * inv);
        *(float2*)(o + 2) = make_float2((a2 + sh[4 * tid + 2]) * inv,
                                        (a3 + sh[4 * tid + 3]) * inv);
    } else if (tail) {
        float* o = out + (size_t)b * LTOT + e0;
        *(float2*)o = make_float2((a0 + sh[4 * tid])     * inv,
                                  (a1 + sh[4 * tid + 1]) * inv);
    }
}

// ---------------------------------------------------------------------------
extern "C" void kernel_launch(void* const* d_in, const int* in_sizes, int n_in,
                              void* d_out, int out_size) {
    const float* sig = (const float*)d_in[0];
    float* out = (float*)d_out;

    k_levelsums<<<NROWS, 256>>>(sig);
    k_scale<<<NTILES, SCT>>>(sig, out);
}

// round 17
// speedup vs baseline: 1.0120x; 1.0120x over previous
#include <cuda_runtime.h>
#include <math.h>

#define LTOT    19530
#define BB      64
#define SS      32
#define NROWS   2048
#define NBISECT 32
#define N4      4882        // full float4-column groups per row (4*4882 = 19528)
#define NTILE_B 39          // 128-wide float4-group tiles per row (39*128=4992 >= 4883)
#define NTILES  (BB * NTILE_B)
#define SCT     128         // k_scale threads per block

// Scratch (__device__ global: allocation-guard compliant)
__device__ float g_pw[NROWS * 8];   // per-row root powers [row][k] = root^k

// ---------------------------------------------------------------------------
// Kernel 1: per-row per-level squared sums + fused bisection (frozen R3 form)
// ---------------------------------------------------------------------------
__device__ __forceinline__ void vec_sq_sum(const float* __restrict__ x,
                                           int lo, int hi, int p,
                                           int tid, float& acc) {
    int a = lo + ((((p - lo) % 4) + 4) % 4);
    if (tid < a - lo) { float v = x[lo + tid]; acc = fmaf(v, v, acc); }
    const int nv = (hi - a) >> 2;
    const float4* __restrict__ xv = (const float4*)(x + a);
    #pragma unroll 4
    for (int i = tid; i < nv; i += 256) {
        float4 v = xv[i];
        acc = fmaf(v.x, v.x, acc);
        acc = fmaf(v.y, v.y, acc);
        acc = fmaf(v.z, v.z, acc);
        acc = fmaf(v.w, v.w, acc);
    }
    const int t0 = a + 4 * nv;
    if (tid < hi - t0) { float v = x[t0 + tid]; acc = fmaf(v, v, acc); }
}

__global__ __launch_bounds__(256) void k_levelsums(const float* __restrict__ sig) {
    const int row = blockIdx.x;
    const int tid = threadIdx.x;
    const float* __restrict__ x = sig + (size_t)row * LTOT;

    float acc[6] = {0.f, 0.f, 0.f, 0.f, 0.f, 0.f};

    const int off[5] = {0, 5, 30, 155, 780};
    #pragma unroll
    for (int k = 0; k < 4; k++)
        for (int i = off[k] + tid; i < off[k + 1]; i += 256) {
            float v = x[i];
            acc[k] = fmaf(v, v, acc[k]);
        }

    const int p = (row & 1) ? 2 : 0;   // row byte base % 16 == 8 for odd rows
    vec_sq_sum(x, 780,  3905, p, tid, acc[4]);
    vec_sq_sum(x, 3905, LTOT, p, tid, acc[5]);

    __shared__ float sm[8][8];
    __shared__ float totals[8];
    const int lane = tid & 31, w = tid >> 5;
    #pragma unroll
    for (int k = 0; k < 6; k++) {
        float v = acc[k];
        #pragma unroll
        for (int o = 16; o > 0; o >>= 1) v += __shfl_down_sync(0xffffffffu, v, o);
        if (lane == 0) sm[w][k] = v;
    }
    __syncthreads();
    if (w == 0) {
        if (lane < 6) {
            float t = 0.f;
            #pragma unroll
            for (int i = 0; i < 8; i++) t += sm[i][lane];
            totals[lane] = t;
        }
        __syncwarp();
        if (lane == 0) {
            float c[7];
            float total = 0.f;
            #pragma unroll
            for (int k = 1; k <= 6; k++) { c[k] = totals[k - 1]; total += c[k]; }
            const float nq  = 1.f + total;
            const float phi = (nq > 4.f) ? (8.f - 16.f / nq) : nq;   // C=4, a=1
            c[0] = 1.f - phi;

            bool fin = true;
            #pragma unroll
            for (int k = 0; k < 7; k++) fin = fin && isfinite(c[k]);

            float lo = 0.f, hi = 2.f;
            #pragma unroll 4
            for (int it = 0; it < NBISECT; it++) {
                const float mid = 0.5f * (lo + hi);
                const float u   = mid * mid;
                float pz = c[6];
                #pragma unroll
                for (int k = 5; k >= 0; k--) pz = fmaf(pz, u, c[k]);
                const bool neg = pz < 0.f;
                lo = neg ? mid : lo;
                hi = neg ? hi  : mid;
            }
            float root = 0.5f * (lo + hi);
            if (!fin) root = 0.f;
            root = fminf(root, 1.f);

            float pw = 1.f;
            g_pw[row * 8 + 0] = 1.f;
            #pragma unroll
            for (int k = 1; k <= 6; k++) { pw *= root; g_pw[row * 8 + k] = pw; }
            g_pw[row * 8 + 7] = 0.f;
        }
    }
}

// ---------------------------------------------------------------------------
// Kernel 2: scale + mean over S. 128-thread blocks, 39 tiles/row. All-LDG.128
// with shifted odd-row loads + smem shift-add fixup. Tail thread sums EVEN
// samples only. Reverse tile order for cross-kernel / cross-replay L2 reuse.
// ---------------------------------------------------------------------------
__device__ __forceinline__ int level_of(int idx) {
    if (idx < 5)    return 1;
    if (idx < 30)   return 2;
    if (idx < 155)  return 3;
    if (idx < 780)  return 4;
    if (idx < 3905) return 5;
    return 6;
}

__global__ __launch_bounds__(SCT, 8) void k_scale(const float* __restrict__ sig,
                                                  float* __restrict__ out) {
    const int rtile = (NTILES - 1) - (int)blockIdx.x;   // high tiles first
    const int b  = rtile / NTILE_B;
    const int tt = rtile - b * NTILE_B;
    const int tid = threadIdx.x;

    __shared__ float spw[SS * 8];
    __shared__ float sh[4 * SCT + 4];   // shifted odd-row sums, by column offset

    #pragma unroll
    for (int i = tid; i < SS * 8; i += SCT)
        spw[i] = g_pw[(size_t)b * SS * 8 + i];
    __syncthreads();

    const int j4 = tt * SCT + tid;
    const int e0 = 4 * j4;
    const bool full = (j4 < N4);
    const bool tail = (j4 == N4);

    const float* __restrict__ base = sig + (size_t)b * SS * LTOT;
    const float inv = 1.f / (float)SS;

    float a0 = 0.f, a1 = 0.f, a2 = 0.f, a3 = 0.f;       // cols e0..e0+3
    float c0 = 0.f, c1 = 0.f, c2 = 0.f, c3 = 0.f;       // odd rows, cols e0+2..e0+5
    float h0 = 0.f, h1 = 0.f;                           // halo: first 2 cols, odd rows

    if (full) {
        const int lv0 = level_of(e0);
        const int lv1 = level_of(e0 + 1);
        const int lv2 = level_of(e0 + 2);
        const int lv3 = level_of(e0 + 3);
        const int lv4 = level_of(e0 + 4);
        const int lv5 = level_of(e0 + 5);

        #pragma unroll
        for (int sb = 0; sb < SS; sb += 8) {
            // 8 x LDG.128, all 16B-aligned, front-batched
            float4 ue[4], uo[4];
            #pragma unroll
            for (int t = 0; t < 4; t++)
                ue[t] = *(const float4*)(base + (size_t)(sb + 2 * t) * LTOT + e0);
            #pragma unroll
            for (int t = 0; t < 4; t++)
                uo[t] = *(const float4*)(base + (size_t)(sb + 2 * t + 1) * LTOT + e0 + 2);
            #pragma unroll
            for (int t = 0; t < 4; t++) {
                const int se = sb + 2 * t, so = se + 1;
                a0 = fmaf(ue[t].x, spw[se * 8 + lv0], a0);
                a1 = fmaf(ue[t].y, spw[se * 8 + lv1], a1);
                a2 = fmaf(ue[t].z, spw[se * 8 + lv2], a2);
                a3 = fmaf(ue[t].w, spw[se * 8 + lv3], a3);
                c0 = fmaf(uo[t].x, spw[so * 8 + lv2], c0);
                c1 = fmaf(uo[t].y, spw[so * 8 + lv3], c1);
                c2 = fmaf(uo[t].z, spw[so * 8 + lv4], c2);
                c3 = fmaf(uo[t].w, spw[so * 8 + lv5], c3);
            }
        }
        if (tid == 0) {
            // halo: odd rows' first two columns of this block's tile
            #pragma unroll
            for (int s = 1; s < SS; s += 2) {
                const float2 v = *(const float2*)(base + (size_t)s * LTOT + e0);
                h0 = fmaf(v.x, spw[s * 8 + lv0], h0);
                h1 = fmaf(v.y, spw[s * 8 + lv1], h1);
            }
        }
    } else if (tail) {
        // cols 19528/19529 (level 6): EVEN rows only — odd rows come from
        // the previous thread's shifted c2/c3 via sh.
        #pragma unroll
        for (int s = 0; s < SS; s += 2) {
            const float2 v = *(const float2*)(base + (size_t)s * LTOT + e0);
            const float  w6 = spw[s * 8 + 6];
            a0 = fmaf(v.x, w6, a0);
            a1 = fmaf(v.y, w6, a1);
        }
    }

    // column-offset shift: thread t's c_i sit at column offset 4t+2+i
    if (tid == 0) { sh[0] = h0; sh[1] = h1; }
    sh[4 * tid + 2] = full ? c0 : 0.f;
    sh[4 * tid + 3] = full ? c1 : 0.f;
    sh[4 * tid + 4] = full ? c2 : 0.f;
    sh[4 * tid + 5] = full ? c3 : 0.f;
    __syncthreads();

    if (full) {
        float* o = out + (size_t)b * LTOT + e0;   // 8B aligned
        *(float2*)o       = make_float2((a0 + sh[4 * tid])     * inv,
                                        (a1 + sh[4 * tid + 1]) * inv);
        *(float2*)(o + 2) = make_float2((a2 + sh[4 * tid + 2]) * inv,
                                        (a3 + sh[4 * tid + 3]) * inv);
    } else if (tail) {
        float* o = out + (size_t)b * LTOT + e0;
        *(float2*)o = make_float2((a0 + sh[4 * tid])     * inv,
                                  (a1 + sh[4 * tid + 1]) * inv);
    }
}

// ---------------------------------------------------------------------------
extern "C" void kernel_launch(void* const* d_in, const int* in_sizes, int n_in,
                              void* d_out, int out_size) {
    const float* sig = (const float*)d_in[0];
    float* out = (float*)d_out;

    k_levelsums<<<NROWS, 256>>>(sig);
    k_scale<<<NTILES, SCT>>>(sig, out);
}